// round 1
// baseline (speedup 1.0000x reference)
#include <cuda_runtime.h>
#include <math.h>

#define TT   1024
#define HH   1024
#define FFN  2048
#define NE   8
#define KSEL 2
#define NP   (TT*KSEL)   // 2048 (token, expert) pairs

#define BM 64
#define BN 64
#define BK 16

// ---------------- scratch (static device globals; no allocation) ------------
__device__ int   g_counts[NE];
__device__ int   g_offsets[NE];
__device__ int   g_slot[NP];          // pair (t*K+k) -> global slot
__device__ int   g_slot_token[NP];    // slot -> token id
__device__ float g_act[(size_t)NP * FFN];   // 16 MB
__device__ float g_y[(size_t)NP * HH];      //  8 MB

// ---------------- routing: count, scan, place (single block) ----------------
__global__ void k_route(const int* __restrict__ sel) {
    __shared__ int s_cnt[NE], s_off[NE], s_cur[NE];
    int tid = threadIdx.x;
    if (tid < NE) s_cnt[tid] = 0;
    __syncthreads();
    for (int p = tid; p < NP; p += blockDim.x)
        atomicAdd(&s_cnt[sel[p]], 1);
    __syncthreads();
    if (tid == 0) {
        int off = 0;
        for (int e = 0; e < NE; e++) { s_off[e] = off; off += s_cnt[e]; }
    }
    __syncthreads();
    if (tid < NE) {
        g_counts[tid]  = s_cnt[tid];
        g_offsets[tid] = s_off[tid];
        s_cur[tid]     = s_off[tid];
    }
    __syncthreads();
    for (int p = tid; p < NP; p += blockDim.x) {
        int e   = sel[p];
        int pos = atomicAdd(&s_cur[e], 1);
        g_slot[p] = pos;
        g_slot_token[pos] = p / KSEL;
    }
}

// ---------------- GEMM1: act = silu(x@w1_gate + b1g) * (x@w1_lin + b1l) -----
// grid: (FFN/BN, maxMtiles, NE). Block computes a BMxBN tile of act for one
// expert, fusing gate and lin halves of w1 so the activation is an epilogue.
__global__ __launch_bounds__(256)
void k_gemm1(const float* __restrict__ x,
             const float* __restrict__ w1,
             const float* __restrict__ b1) {
    int e   = blockIdx.z;
    int cnt = g_counts[e];
    int m0  = blockIdx.y * BM;
    if (m0 >= cnt) return;
    int off = g_offsets[e];
    int n0  = blockIdx.x * BN;   // f-slice [n0, n0+BN)

    __shared__ float As[BK][BM];
    __shared__ float Bg[BK][BN];
    __shared__ float Bl[BK][BN];

    int tid = threadIdx.x;
    int tx = tid & 15, ty = tid >> 4;   // 16x16 thread grid, 4x4 micro-tiles
    int lr = tid >> 2, lq = tid & 3;    // loader: row 0..63, quad 0..3

    int m = m0 + lr;
    const float* arow = (m < cnt)
        ? (x + (size_t)g_slot_token[off + m] * HH) : (const float*)0;
    const float* w1e  = w1 + (size_t)e * (2 * FFN) * HH;
    const float* grow = w1e + (size_t)(n0 + lr) * HH;
    const float* lrow = w1e + (size_t)(FFN + n0 + lr) * HH;

    float accg[4][4] = {{0.f}}, accl[4][4] = {{0.f}};

    for (int k0 = 0; k0 < HH; k0 += BK) {
        float4 av = make_float4(0.f, 0.f, 0.f, 0.f);
        if (arow) av = *(const float4*)(arow + k0 + lq * 4);
        float4 gv = *(const float4*)(grow + k0 + lq * 4);
        float4 lv = *(const float4*)(lrow + k0 + lq * 4);
        __syncthreads();
        As[lq*4+0][lr] = av.x; As[lq*4+1][lr] = av.y;
        As[lq*4+2][lr] = av.z; As[lq*4+3][lr] = av.w;
        Bg[lq*4+0][lr] = gv.x; Bg[lq*4+1][lr] = gv.y;
        Bg[lq*4+2][lr] = gv.z; Bg[lq*4+3][lr] = gv.w;
        Bl[lq*4+0][lr] = lv.x; Bl[lq*4+1][lr] = lv.y;
        Bl[lq*4+2][lr] = lv.z; Bl[lq*4+3][lr] = lv.w;
        __syncthreads();
        #pragma unroll
        for (int k = 0; k < BK; k++) {
            float4 a4  = *(const float4*)&As[k][ty * 4];
            float4 bg4 = *(const float4*)&Bg[k][tx * 4];
            float4 bl4 = *(const float4*)&Bl[k][tx * 4];
            float aa[4]  = {a4.x, a4.y, a4.z, a4.w};
            float bgv[4] = {bg4.x, bg4.y, bg4.z, bg4.w};
            float blv[4] = {bl4.x, bl4.y, bl4.z, bl4.w};
            #pragma unroll
            for (int i = 0; i < 4; i++)
                #pragma unroll
                for (int j = 0; j < 4; j++) {
                    accg[i][j] += aa[i] * bgv[j];
                    accl[i][j] += aa[i] * blv[j];
                }
        }
    }

    const float* b1e = b1 + (size_t)e * (2 * FFN);
    #pragma unroll
    for (int i = 0; i < 4; i++) {
        int mm = m0 + ty * 4 + i;
        if (mm >= cnt) continue;
        size_t s = (size_t)(off + mm);
        #pragma unroll
        for (int j = 0; j < 4; j++) {
            int f   = n0 + tx * 4 + j;
            float g = accg[i][j] + b1e[f];
            float l = accl[i][j] + b1e[FFN + f];
            float sg = g / (1.f + expf(-g));   // silu
            g_act[s * FFN + f] = sg * l;
        }
    }
}

// ---------------- GEMM2: y = act @ w2^T + b2 ---------------------------------
// grid: (HH/BN, maxMtiles, NE)
__global__ __launch_bounds__(256)
void k_gemm2(const float* __restrict__ w2,
             const float* __restrict__ b2) {
    int e   = blockIdx.z;
    int cnt = g_counts[e];
    int m0  = blockIdx.y * BM;
    if (m0 >= cnt) return;
    int off = g_offsets[e];
    int n0  = blockIdx.x * BN;   // h-slice

    __shared__ float As[BK][BM];
    __shared__ float Bs[BK][BN];

    int tid = threadIdx.x;
    int tx = tid & 15, ty = tid >> 4;
    int lr = tid >> 2, lq = tid & 3;

    int m = m0 + lr;
    const float* arow = (m < cnt)
        ? (g_act + (size_t)(off + m) * FFN) : (const float*)0;
    const float* brow = w2 + (size_t)e * HH * FFN + (size_t)(n0 + lr) * FFN;

    float acc[4][4] = {{0.f}};

    for (int k0 = 0; k0 < FFN; k0 += BK) {
        float4 av = make_float4(0.f, 0.f, 0.f, 0.f);
        if (arow) av = *(const float4*)(arow + k0 + lq * 4);
        float4 bv = *(const float4*)(brow + k0 + lq * 4);
        __syncthreads();
        As[lq*4+0][lr] = av.x; As[lq*4+1][lr] = av.y;
        As[lq*4+2][lr] = av.z; As[lq*4+3][lr] = av.w;
        Bs[lq*4+0][lr] = bv.x; Bs[lq*4+1][lr] = bv.y;
        Bs[lq*4+2][lr] = bv.z; Bs[lq*4+3][lr] = bv.w;
        __syncthreads();
        #pragma unroll
        for (int k = 0; k < BK; k++) {
            float4 a4 = *(const float4*)&As[k][ty * 4];
            float4 b4 = *(const float4*)&Bs[k][tx * 4];
            float aa[4] = {a4.x, a4.y, a4.z, a4.w};
            float bb[4] = {b4.x, b4.y, b4.z, b4.w};
            #pragma unroll
            for (int i = 0; i < 4; i++)
                #pragma unroll
                for (int j = 0; j < 4; j++)
                    acc[i][j] += aa[i] * bb[j];
        }
    }

    const float* b2e = b2 + (size_t)e * HH;
    #pragma unroll
    for (int i = 0; i < 4; i++) {
        int mm = m0 + ty * 4 + i;
        if (mm >= cnt) continue;
        size_t s = (size_t)(off + mm);
        #pragma unroll
        for (int j = 0; j < 4; j++) {
            int h = n0 + tx * 4 + j;
            g_y[s * HH + h] = acc[i][j] + b2e[h];
        }
    }
}

// ---------------- scatter: out[t] = sum_k scale[t,k] * y[slot(t,k)] ---------
__global__ void k_scatter(const float* __restrict__ scales,
                          float* __restrict__ out) {
    int t  = blockIdx.x;
    int s0 = g_slot[t * KSEL + 0];
    int s1 = g_slot[t * KSEL + 1];
    float c0 = scales[t * KSEL + 0];
    float c1 = scales[t * KSEL + 1];
    const float* y0 = g_y + (size_t)s0 * HH;
    const float* y1 = g_y + (size_t)s1 * HH;
    for (int h = threadIdx.x; h < HH; h += blockDim.x)
        out[(size_t)t * HH + h] = c0 * y0[h] + c1 * y1[h];
}

// ---------------- launch -----------------------------------------------------
extern "C" void kernel_launch(void* const* d_in, const int* in_sizes, int n_in,
                              void* d_out, int out_size) {
    const float* x    = (const float*)d_in[0];
    const int*   sel  = (const int*)  d_in[1];
    const float* scal = (const float*)d_in[2];
    const float* w1   = (const float*)d_in[3];
    const float* b1   = (const float*)d_in[4];
    const float* w2   = (const float*)d_in[5];
    const float* b2   = (const float*)d_in[6];
    float* out = (float*)d_out;

    k_route<<<1, 256>>>(sel);

    dim3 g1(FFN / BN, NP / BM, NE);   // (32, 32, 8); empty m-tiles exit early
    k_gemm1<<<g1, 256>>>(x, w1, b1);

    dim3 g2(HH / BN, NP / BM, NE);    // (16, 32, 8)
    k_gemm2<<<g2, 256>>>(w2, b2);

    k_scatter<<<TT, 256>>>(scal, out);
}

// round 4
// speedup vs baseline: 1.9552x; 1.9552x over previous
#include <cuda_runtime.h>
#include <cuda_bf16.h>
#include <cstdint>
#include <math.h>

#define TT   1024
#define HH   1024
#define FFN  2048
#define NE   8
#define KSEL 2
#define NP   (TT*KSEL)

// ---------------------------------------------------------------------------
// scratch (static device globals; no allocation anywhere)
// ---------------------------------------------------------------------------
__device__ int   g_counts[NE];
__device__ int   g_offsets[NE];
__device__ int   g_slot[NP];            // pair -> slot
__device__ int   g_slot_token[NP];      // slot -> token
__device__ int   g_slot_expert[NP];     // slot -> expert
__device__ __nv_bfloat16 g_w1h[(size_t)NE * 2 * FFN * HH];
__device__ __nv_bfloat16 g_w1l[(size_t)NE * 2 * FFN * HH];
__device__ __nv_bfloat16 g_w2h[(size_t)NE * HH * FFN];
__device__ __nv_bfloat16 g_w2l[(size_t)NE * HH * FFN];
__device__ __nv_bfloat16 g_xh[(size_t)TT * HH];
__device__ __nv_bfloat16 g_xl[(size_t)TT * HH];
__device__ float         g_h1[(size_t)NP * 2 * FFN];
__device__ __nv_bfloat16 g_acth[(size_t)NP * FFN];
__device__ __nv_bfloat16 g_actl[(size_t)NP * FFN];
__device__ float         g_y[(size_t)NP * HH];

// ---------------------------------------------------------------------------
// helpers
// ---------------------------------------------------------------------------
__device__ __forceinline__ uint32_t smem_u32(const void* p) {
    uint32_t a;
    asm("{ .reg .u64 t; cvta.to.shared.u64 t, %1; cvt.u32.u64 %0, t; }"
        : "=r"(a) : "l"(p));
    return a;
}

#define CP16(dst, src) \
    asm volatile("cp.async.cg.shared.global [%0], [%1], 16;" \
                 :: "r"(dst), "l"((const void*)(src)) : "memory")
#define CP_COMMIT() asm volatile("cp.async.commit_group;" ::: "memory")
#define CP_WAIT(n)  asm volatile("cp.async.wait_group %0;" :: "n"(n) : "memory")

#define LDM_X4(r0, r1, r2, r3, addr) \
    asm volatile("ldmatrix.sync.aligned.m8n8.x4.shared.b16 {%0,%1,%2,%3}, [%4];" \
                 : "=r"(r0), "=r"(r1), "=r"(r2), "=r"(r3) : "r"(addr))

#define MMA_BF16(d, a, b0v, b1v) \
    asm volatile("mma.sync.aligned.m16n8k16.row.col.f32.bf16.bf16.f32 " \
                 "{%0,%1,%2,%3}, {%4,%5,%6,%7}, {%8,%9}, {%0,%1,%2,%3};" \
                 : "+f"((d)[0]), "+f"((d)[1]), "+f"((d)[2]), "+f"((d)[3]) \
                 : "r"((a)[0]), "r"((a)[1]), "r"((a)[2]), "r"((a)[3]), \
                   "r"(b0v), "r"(b1v))

// ---------------------------------------------------------------------------
// routing
// ---------------------------------------------------------------------------
__global__ void k_route(const int* __restrict__ sel) {
    __shared__ int s_cnt[NE], s_off[NE], s_cur[NE];
    int tid = threadIdx.x;
    if (tid < NE) s_cnt[tid] = 0;
    __syncthreads();
    for (int p = tid; p < NP; p += blockDim.x) atomicAdd(&s_cnt[sel[p]], 1);
    __syncthreads();
    if (tid == 0) {
        int off = 0;
        for (int e = 0; e < NE; e++) { s_off[e] = off; off += s_cnt[e]; }
    }
    __syncthreads();
    if (tid < NE) {
        g_counts[tid] = s_cnt[tid];
        g_offsets[tid] = s_off[tid];
        s_cur[tid] = s_off[tid];
    }
    __syncthreads();
    for (int p = tid; p < NP; p += blockDim.x) {
        int e = sel[p];
        int pos = atomicAdd(&s_cur[e], 1);
        g_slot[p] = pos;
        g_slot_token[pos] = p / KSEL;
        g_slot_expert[pos] = e;
    }
}

// ---------------------------------------------------------------------------
// fp32 -> bf16 hi/lo split
// ---------------------------------------------------------------------------
__global__ void k_split(const float* __restrict__ src,
                        __nv_bfloat16* __restrict__ hi,
                        __nv_bfloat16* __restrict__ lo, size_t n) {
    size_t i0 = ((size_t)blockIdx.x * blockDim.x + threadIdx.x) * 4;
    size_t stride = (size_t)gridDim.x * blockDim.x * 4;
    for (size_t j = i0; j < n; j += stride) {
        float4 v = *(const float4*)(src + j);
        __nv_bfloat16 h0 = __float2bfloat16(v.x), h1 = __float2bfloat16(v.y);
        __nv_bfloat16 h2 = __float2bfloat16(v.z), h3 = __float2bfloat16(v.w);
        __nv_bfloat16 l0 = __float2bfloat16(v.x - __bfloat162float(h0));
        __nv_bfloat16 l1 = __float2bfloat16(v.y - __bfloat162float(h1));
        __nv_bfloat16 l2 = __float2bfloat16(v.z - __bfloat162float(h2));
        __nv_bfloat16 l3 = __float2bfloat16(v.w - __bfloat162float(h3));
        *(__nv_bfloat162*)(hi + j)     = __nv_bfloat162(h0, h1);
        *(__nv_bfloat162*)(hi + j + 2) = __nv_bfloat162(h2, h3);
        *(__nv_bfloat162*)(lo + j)     = __nv_bfloat162(l0, l1);
        *(__nv_bfloat162*)(lo + j + 2) = __nv_bfloat162(l2, l3);
    }
}

// ---------------------------------------------------------------------------
// grouped bf16-split GEMM via mma.sync:
//   C[off+m, n] = sum_k A[arow(m), k] * B[e, n, k]  (+bias)
// block tile 128x128, Kc=32, 8 warps each 32x64.
// smem rows padded to 80B (64B data + 16B) -> conflict-free ldmatrix.
// ---------------------------------------------------------------------------
#define ROWB   80
#define A_H    0
#define A_L    10240
#define B_H    20480
#define B_L    30720
#define STAGE  40960
#define GEMM_SMEM (2 * STAGE)

__global__ __launch_bounds__(256)
void k_gemm_mma(const __nv_bfloat16* __restrict__ Ah,
                const __nv_bfloat16* __restrict__ Al,
                const int* __restrict__ rowmap,
                const __nv_bfloat16* __restrict__ Bh,
                const __nv_bfloat16* __restrict__ Bl,
                const float* __restrict__ bias,
                float* __restrict__ C,
                int Ntot, int K) {
    int e   = blockIdx.z;
    int cnt = g_counts[e];
    int m0  = blockIdx.y * 128;
    if (m0 >= cnt) return;
    int off = g_offsets[e];
    int n0  = blockIdx.x * 128;

    extern __shared__ char smem[];
    uint32_t sb = smem_u32(smem);
    int tid = threadIdx.x, wid = tid >> 5, lid = tid & 31;
    int wm = wid & 3, wn = wid >> 2;     // warp tile (wm*32, wn*64)

    __shared__ int s_arow[128];
    if (tid < 128) {
        int m = m0 + tid;
        int mm = (m < cnt) ? m : (cnt - 1);
        s_arow[tid] = rowmap ? rowmap[off + mm] : (off + mm);
    }
    __syncthreads();

    size_t bbase = (size_t)e * Ntot * K;

    auto load_stage = [&](int kc, int s) {
        uint32_t base = sb + (uint32_t)s * STAGE;
        int k0 = kc * 32;
#pragma unroll
        for (int j = 0; j < 2; j++) {
            int c = tid + j * 256;               // 0..511
            int row = c >> 2, ch = c & 3;
            uint32_t so = (uint32_t)(row * ROWB + ch * 16);
            size_t ko = (size_t)k0 + ch * 8;
            size_t ao = (size_t)s_arow[row] * K + ko;
            CP16(base + A_H + so, Ah + ao);
            CP16(base + A_L + so, Al + ao);
            size_t bo = bbase + (size_t)(n0 + row) * K + ko;
            CP16(base + B_H + so, Bh + bo);
            CP16(base + B_L + so, Bl + bo);
        }
        CP_COMMIT();
    };

    float acc[2][8][4];
#pragma unroll
    for (int i = 0; i < 2; i++)
#pragma unroll
        for (int j = 0; j < 8; j++)
#pragma unroll
            for (int q = 0; q < 4; q++) acc[i][j][q] = 0.f;

    // ldmatrix lane addressing (within warp)
    // A 16x16 tile: lanes 0-15 -> row lane, col 0; lanes 16-31 -> row lane-16, col +8
    uint32_t a_row = (uint32_t)(lid & 15);
    uint32_t a_colb = (uint32_t)((lid >> 4) * 16);
    // B pair of n8k16 tiles: nrow = (lane>>4)*8 + (lane&7); col = ((lane>>3)&1)*16
    uint32_t b_row = (uint32_t)(((lid >> 4) << 3) + (lid & 7));
    uint32_t b_colb = (uint32_t)(((lid >> 3) & 1) * 16);

    int iters = K >> 5;
    load_stage(0, 0);

    for (int kc = 0; kc < iters; kc++) {
        int s = kc & 1;
        if (kc + 1 < iters) {
            load_stage(kc + 1, s ^ 1);
            CP_WAIT(1);
        } else {
            CP_WAIT(0);
        }
        __syncthreads();

        uint32_t base = sb + (uint32_t)s * STAGE;
#pragma unroll
        for (int ks = 0; ks < 2; ks++) {
            uint32_t kb = (uint32_t)(ks * 32);
            uint32_t afh[2][4], afl[2][4];
#pragma unroll
            for (int mt = 0; mt < 2; mt++) {
                uint32_t ro = (uint32_t)((wm * 32 + mt * 16 + a_row) * ROWB) + kb + a_colb;
                LDM_X4(afh[mt][0], afh[mt][1], afh[mt][2], afh[mt][3], base + A_H + ro);
                LDM_X4(afl[mt][0], afl[mt][1], afl[mt][2], afl[mt][3], base + A_L + ro);
            }
            uint32_t bfh[4][4], bfl[4][4];
#pragma unroll
            for (int p = 0; p < 4; p++) {
                uint32_t ro = (uint32_t)((wn * 64 + p * 16 + b_row) * ROWB) + kb + b_colb;
                LDM_X4(bfh[p][0], bfh[p][1], bfh[p][2], bfh[p][3], base + B_H + ro);
                LDM_X4(bfl[p][0], bfl[p][1], bfl[p][2], bfl[p][3], base + B_L + ro);
            }
#pragma unroll
            for (int mt = 0; mt < 2; mt++) {
#pragma unroll
                for (int p = 0; p < 4; p++) {
                    // ntile 2p  : regs {[0],[1]} ; ntile 2p+1: regs {[2],[3]}
                    MMA_BF16(acc[mt][2 * p],     afh[mt], bfh[p][0], bfh[p][1]);
                    MMA_BF16(acc[mt][2 * p],     afh[mt], bfl[p][0], bfl[p][1]);
                    MMA_BF16(acc[mt][2 * p],     afl[mt], bfh[p][0], bfh[p][1]);
                    MMA_BF16(acc[mt][2 * p + 1], afh[mt], bfh[p][2], bfh[p][3]);
                    MMA_BF16(acc[mt][2 * p + 1], afh[mt], bfl[p][2], bfl[p][3]);
                    MMA_BF16(acc[mt][2 * p + 1], afl[mt], bfh[p][2], bfh[p][3]);
                }
            }
        }
        __syncthreads();
    }

    // epilogue: acc frag (m16n8): c0,c1 @ (row=lid/4, col=2*(lid%4)); c2,c3 @ row+8
    int rbase = m0 + wm * 32 + (lid >> 2);
    int cbase = n0 + wn * 64 + (lid & 3) * 2;
#pragma unroll
    for (int mt = 0; mt < 2; mt++) {
        int r1 = rbase + mt * 16;
        int r2 = r1 + 8;
#pragma unroll
        for (int nt = 0; nt < 8; nt++) {
            int col = cbase + nt * 8;
            float b0 = 0.f, b1 = 0.f;
            if (bias) {
                const float* bp = bias + (size_t)e * Ntot + col;
                b0 = bp[0]; b1 = bp[1];
            }
            if (r1 < cnt) {
                float* cp = C + (size_t)(off + r1) * Ntot + col;
                cp[0] = acc[mt][nt][0] + b0;
                cp[1] = acc[mt][nt][1] + b1;
            }
            if (r2 < cnt) {
                float* cp = C + (size_t)(off + r2) * Ntot + col;
                cp[0] = acc[mt][nt][2] + b0;
                cp[1] = acc[mt][nt][3] + b1;
            }
        }
    }
}

// ---------------------------------------------------------------------------
// activation: act = silu(h1_gate + b1g) * (h1_lin + b1l), emit bf16 hi/lo
// ---------------------------------------------------------------------------
__global__ void k_act(const float* __restrict__ b1) {
    int s = blockIdx.x;
    int e = g_slot_expert[s];
    const float* h1 = g_h1 + (size_t)s * 2 * FFN;
    const float* be = b1 + (size_t)e * 2 * FFN;
    __nv_bfloat16* ah = g_acth + (size_t)s * FFN;
    __nv_bfloat16* al = g_actl + (size_t)s * FFN;
    for (int f = threadIdx.x * 4; f < FFN; f += blockDim.x * 4) {
        float4 g4 = *(const float4*)(h1 + f);
        float4 bg = *(const float4*)(be + f);
        float4 l4 = *(const float4*)(h1 + FFN + f);
        float4 bl = *(const float4*)(be + FFN + f);
        float gv[4] = {g4.x + bg.x, g4.y + bg.y, g4.z + bg.z, g4.w + bg.w};
        float lv[4] = {l4.x + bl.x, l4.y + bl.y, l4.z + bl.z, l4.w + bl.w};
        __nv_bfloat16 h[4], l[4];
#pragma unroll
        for (int j = 0; j < 4; j++) {
            float a = (gv[j] / (1.f + expf(-gv[j]))) * lv[j];
            h[j] = __float2bfloat16(a);
            l[j] = __float2bfloat16(a - __bfloat162float(h[j]));
        }
        *(__nv_bfloat162*)(ah + f)     = __nv_bfloat162(h[0], h[1]);
        *(__nv_bfloat162*)(ah + f + 2) = __nv_bfloat162(h[2], h[3]);
        *(__nv_bfloat162*)(al + f)     = __nv_bfloat162(l[0], l[1]);
        *(__nv_bfloat162*)(al + f + 2) = __nv_bfloat162(l[2], l[3]);
    }
}

// ---------------------------------------------------------------------------
// scatter: out[t] = sum_k scale[t,k] * y[slot(t,k)]
// ---------------------------------------------------------------------------
__global__ void k_scatter(const float* __restrict__ scales,
                          float* __restrict__ out) {
    int t = blockIdx.x;
    int s0 = g_slot[t * KSEL + 0];
    int s1 = g_slot[t * KSEL + 1];
    float c0 = scales[t * KSEL + 0];
    float c1 = scales[t * KSEL + 1];
    const float* y0 = g_y + (size_t)s0 * HH;
    const float* y1 = g_y + (size_t)s1 * HH;
    for (int h = threadIdx.x; h < HH; h += blockDim.x)
        out[(size_t)t * HH + h] = c0 * y0[h] + c1 * y1[h];
}

// ---------------------------------------------------------------------------
// launch
// ---------------------------------------------------------------------------
extern "C" void kernel_launch(void* const* d_in, const int* in_sizes, int n_in,
                              void* d_out, int out_size) {
    const float* x    = (const float*)d_in[0];
    const int*   sel  = (const int*)  d_in[1];
    const float* scal = (const float*)d_in[2];
    const float* w1   = (const float*)d_in[3];
    const float* b1   = (const float*)d_in[4];
    const float* w2   = (const float*)d_in[5];
    const float* b2   = (const float*)d_in[6];
    float* out = (float*)d_out;

    cudaFuncSetAttribute(k_gemm_mma, cudaFuncAttributeMaxDynamicSharedMemorySize,
                         GEMM_SMEM);

    k_route<<<1, 256>>>(sel);

    __nv_bfloat16 *w1h, *w1l, *w2h, *w2l, *xh, *xl, *acth, *actl;
    float *h1p, *yp;
    int *rmap;
    cudaGetSymbolAddress((void**)&w1h, g_w1h);
    cudaGetSymbolAddress((void**)&w1l, g_w1l);
    cudaGetSymbolAddress((void**)&w2h, g_w2h);
    cudaGetSymbolAddress((void**)&w2l, g_w2l);
    cudaGetSymbolAddress((void**)&xh,  g_xh);
    cudaGetSymbolAddress((void**)&xl,  g_xl);
    cudaGetSymbolAddress((void**)&acth, g_acth);
    cudaGetSymbolAddress((void**)&actl, g_actl);
    cudaGetSymbolAddress((void**)&h1p, g_h1);
    cudaGetSymbolAddress((void**)&yp,  g_y);
    cudaGetSymbolAddress((void**)&rmap, g_slot_token);

    k_split<<<2048, 256>>>(w1, w1h, w1l, (size_t)NE * 2 * FFN * HH);
    k_split<<<2048, 256>>>(w2, w2h, w2l, (size_t)NE * HH * FFN);
    k_split<<<512, 256>>>(x,  xh,  xl,  (size_t)TT * HH);

    // GEMM1: h1[slot, 0..4096) = x(token) @ w1[e]^T
    dim3 g1(2 * FFN / 128, NP / 128, NE);   // (32, 16, 8)
    k_gemm_mma<<<g1, 256, GEMM_SMEM>>>(xh, xl, rmap, w1h, w1l,
                                       (const float*)nullptr, h1p,
                                       2 * FFN, HH);

    k_act<<<NP, 256>>>(b1);

    // GEMM2: y[slot, 0..1024) = act @ w2[e]^T + b2
    dim3 g2(HH / 128, NP / 128, NE);        // (8, 16, 8)
    k_gemm_mma<<<g2, 256, GEMM_SMEM>>>(acth, actl, (const int*)nullptr,
                                       w2h, w2l, b2, yp, HH, FFN);

    k_scatter<<<TT, 256>>>(scal, out);
}